// round 4
// baseline (speedup 1.0000x reference)
#include <cuda_runtime.h>

// CosineSim3D factorized, full-grid 3-kernel pipeline:
//   K1: g_part[b][p][:] = sum over 128 b-rows of b_row / max(|b_row|, sqrt(eps))
//   K2: s_b = sum_p g_part ; g_scores[b][n] = (a_n . s_b) / max(|a_n|, sqrt(eps))
//   K3: per-CTA redundant softmax over g_scores[b][:], write 128-row out slice
//
// a, b : [128, 1024, 300] fp32   out : [128, 1024, 300] fp32

#define BATCH   128
#define NROWS   1024
#define DIM     300
#define NF4     75           // 300/4
#define NSUB    8            // CTAs per batch in K1/K2/K3
#define RSUB    (NROWS/NSUB) // 128 rows per CTA
#define EPSV    1e-7f

// scratch (no cudaMalloc allowed)
__device__ float4 g_part4[BATCH * NSUB * NF4];   // 1.2 MB partial sums
__device__ float  g_scores[BATCH * NROWS];       // 512 KB raw scores

__device__ __forceinline__ float dot4(float4 x, float4 y) {
    return x.x * y.x + x.y * y.y + x.z * y.z + x.w * y.w;
}
__device__ __forceinline__ void fma4(float4& a, float4 v, float s) {
    a.x += v.x * s; a.y += v.y * s; a.z += v.z * s; a.w += v.w * s;
}
__device__ __forceinline__ void add4(float4& a, float4 v) {
    a.x += v.x; a.y += v.y; a.z += v.z; a.w += v.w;
}

// ---------------------------------------------------------------------------
// K1: partial normalized-b sums.  grid = 1024 (batch*8), block = 256 (8 warps)
// ---------------------------------------------------------------------------
__global__ __launch_bounds__(256) void partial_b_kernel(const float* __restrict__ b)
{
    const int batch = blockIdx.x >> 3;
    const int sub   = blockIdx.x & 7;
    const int warp  = threadIdx.x >> 5;
    const int lane  = threadIdx.x & 31;

    const float4 zero4 = make_float4(0.f, 0.f, 0.f, 0.f);
    const float4* b4 = reinterpret_cast<const float4*>(
        b + (size_t)batch * NROWS * DIM);

    float4 acc0 = zero4, acc1 = zero4, acc2 = zero4;

    const int r0 = sub * RSUB;
    for (int r = r0 + warp; r < r0 + RSUB; r += 8) {
        const float4* row = b4 + r * NF4;
        const float4 v0 = __ldg(row + lane);
        const float4 v1 = __ldg(row + lane + 32);
        const float4 v2 = (lane < NF4 - 64) ? __ldg(row + lane + 64) : zero4;
        float ss = dot4(v0, v0) + dot4(v1, v1) + dot4(v2, v2);
#pragma unroll
        for (int o = 16; o > 0; o >>= 1)
            ss += __shfl_xor_sync(0xffffffffu, ss, o);
        const float inv = rsqrtf(fmaxf(ss, EPSV));
        fma4(acc0, v0, inv);
        fma4(acc1, v1, inv);
        fma4(acc2, v2, inv);
    }

    // cross-warp reduce (8 warps)
    __shared__ float4 sw4[8][NF4 + 1];
    sw4[warp][lane]      = acc0;
    sw4[warp][lane + 32] = acc1;
    if (lane < NF4 - 64) sw4[warp][lane + 64] = acc2;
    __syncthreads();

    float4* dst = g_part4 + (batch * NSUB + sub) * NF4;
    for (int j = threadIdx.x; j < NF4; j += blockDim.x) {
        float4 t = sw4[0][j];
#pragma unroll
        for (int w = 1; w < 8; w++) add4(t, sw4[w][j]);
        dst[j] = t;
    }
}

// ---------------------------------------------------------------------------
// K2: fold partials -> s_b, score a rows.  grid = 1024, block = 256
// ---------------------------------------------------------------------------
__global__ __launch_bounds__(256) void score_kernel(const float* __restrict__ a)
{
    const int batch = blockIdx.x >> 3;
    const int sub   = blockIdx.x & 7;
    const int warp  = threadIdx.x >> 5;
    const int lane  = threadIdx.x & 31;

    const float4 zero4 = make_float4(0.f, 0.f, 0.f, 0.f);

    __shared__ float4 ssh4[NF4];
    const float4* part = g_part4 + batch * NSUB * NF4;
    for (int j = threadIdx.x; j < NF4; j += blockDim.x) {
        float4 t = part[j];
#pragma unroll
        for (int p = 1; p < NSUB; p++) add4(t, part[p * NF4 + j]);
        ssh4[j] = t;
    }
    __syncthreads();

    const float4 s0 = ssh4[lane];
    const float4 s1 = ssh4[lane + 32];
    const float4 s2 = (lane < NF4 - 64) ? ssh4[lane + 64] : zero4;

    const float4* a4 = reinterpret_cast<const float4*>(
        a + (size_t)batch * NROWS * DIM);

    const int r0 = sub * RSUB;
    for (int r = r0 + warp; r < r0 + RSUB; r += 8) {
        const float4* row = a4 + r * NF4;
        const float4 v0 = __ldg(row + lane);
        const float4 v1 = __ldg(row + lane + 32);
        const float4 v2 = (lane < NF4 - 64) ? __ldg(row + lane + 64) : zero4;
        float dot = dot4(v0, s0) + dot4(v1, s1) + dot4(v2, s2);
        float ss  = dot4(v0, v0) + dot4(v1, v1) + dot4(v2, v2);
#pragma unroll
        for (int o = 16; o > 0; o >>= 1) {
            dot += __shfl_xor_sync(0xffffffffu, dot, o);
            ss  += __shfl_xor_sync(0xffffffffu, ss,  o);
        }
        if (lane == 0)
            g_scores[batch * NROWS + r] = dot * rsqrtf(fmaxf(ss, EPSV));
    }
}

// ---------------------------------------------------------------------------
// K3: redundant per-CTA softmax + slice write.  grid = 1024, block = 1024
// ---------------------------------------------------------------------------
__global__ __launch_bounds__(1024) void softmax_write_kernel(float* __restrict__ out)
{
    const int batch = blockIdx.x >> 3;
    const int sub   = blockIdx.x & 7;
    const int warp  = threadIdx.x >> 5;
    const int lane  = threadIdx.x & 31;

    __shared__ float probs[NROWS];
    __shared__ float red[32];

    const float x = __ldg(g_scores + batch * NROWS + threadIdx.x);

    // block max
    float m = x;
#pragma unroll
    for (int o = 16; o > 0; o >>= 1)
        m = fmaxf(m, __shfl_xor_sync(0xffffffffu, m, o));
    if (lane == 0) red[warp] = m;
    __syncthreads();
    if (warp == 0) {
        float t = red[lane];
#pragma unroll
        for (int o = 16; o > 0; o >>= 1)
            t = fmaxf(t, __shfl_xor_sync(0xffffffffu, t, o));
        if (lane == 0) red[0] = t;
    }
    __syncthreads();
    const float M = red[0];

    const float e = __expf(x - M);

    // block sum
    float sum = e;
#pragma unroll
    for (int o = 16; o > 0; o >>= 1)
        sum += __shfl_xor_sync(0xffffffffu, sum, o);
    __syncthreads();                 // red[] reuse barrier
    if (lane == 0) red[warp] = sum;
    __syncthreads();
    if (warp == 0) {
        float t = red[lane];
#pragma unroll
        for (int o = 16; o > 0; o >>= 1)
            t += __shfl_xor_sync(0xffffffffu, t, o);
        if (lane == 0) red[0] = t;
    }
    __syncthreads();

    probs[threadIdx.x] = e * __frcp_rn(red[0]);
    __syncthreads();

    // write this CTA's 128-row slice: 128 * 75 = 9600 float4
    float4* o4 = reinterpret_cast<float4*>(out)
               + (size_t)batch * NROWS * NF4 + sub * RSUB * NF4;
    const int rbase = sub * RSUB;
#pragma unroll 2
    for (int i = threadIdx.x; i < RSUB * NF4; i += 1024) {
        const float p = probs[rbase + i / NF4];
        o4[i] = make_float4(p, p, p, p);
    }
}

// ---------------------------------------------------------------------------
extern "C" void kernel_launch(void* const* d_in, const int* in_sizes, int n_in,
                              void* d_out, int out_size)
{
    const float* a = (const float*)d_in[0];
    const float* b = (const float*)d_in[1];
    float* out = (float*)d_out;

    partial_b_kernel<<<BATCH * NSUB, 256>>>(b);
    score_kernel<<<BATCH * NSUB, 256>>>(a);
    softmax_write_kernel<<<BATCH * NSUB, 1024>>>(out);
}